// round 1
// baseline (speedup 1.0000x reference)
#include <cuda_runtime.h>

// ---------------------------------------------------------------------------
// ModulatedConv2d (StyleGAN2-style) on GB300
//   B=8, Cin=512, Cout=512, k=3, H=W=64, WDIM=512
// Pipeline:
//   1) style_kernel : s[b,c] = dot(w[b,:], affine_w[c,:]) + affine_b[c] + 1
//   2) demod_kernel : d[b,co] = rsqrt( sum_{cin,t} (weight*s)^2 + 1e-8 )
//   3) wmod_kernel  : g_wmod[b,co,cin,t] = weight * s * d
//   4) conv_kernel  : grouped 3x3 conv + noise + bias + leaky(0.2)
// ---------------------------------------------------------------------------

#define B_    8
#define CIN   512
#define COUT  512
#define HW    64
#define WDIM  512
#define KK    9      // 3x3 taps

// Scratch (allocation-free rule: __device__ globals)
__device__ float g_s[B_ * CIN];                 // style
__device__ float g_d[B_ * COUT];                // demod scale
__device__ float g_wmod[B_ * COUT * CIN * KK];  // 75.5 MB modulated weights

// ---------------------------------------------------------------------------
// 1) style: one warp per (b, c)
// ---------------------------------------------------------------------------
__global__ void style_kernel(const float* __restrict__ w,
                             const float* __restrict__ aw,
                             const float* __restrict__ ab) {
    int gwarp = (blockIdx.x * blockDim.x + threadIdx.x) >> 5;
    int lane  = threadIdx.x & 31;
    if (gwarp >= B_ * CIN) return;
    int b = gwarp / CIN;
    int c = gwarp % CIN;
    const float* wr = w  + b * WDIM;
    const float* ar = aw + c * WDIM;
    float sum = 0.f;
    #pragma unroll 4
    for (int k = lane; k < WDIM; k += 32) sum += wr[k] * ar[k];
    #pragma unroll
    for (int o = 16; o > 0; o >>= 1) sum += __shfl_xor_sync(0xffffffffu, sum, o);
    if (lane == 0) g_s[gwarp] = sum + ab[c] + 1.0f;
}

// ---------------------------------------------------------------------------
// 2) demod: one 128-thread block per (b, co)
// ---------------------------------------------------------------------------
__global__ void demod_kernel(const float* __restrict__ weight) {
    int co = blockIdx.x;
    int b  = blockIdx.y;
    int tid = threadIdx.x;
    const float* wr = weight + co * (CIN * KK);
    const float* sr = g_s + b * CIN;
    float sum = 0.f;
    for (int j = tid; j < CIN * KK; j += 128) {
        float v = wr[j] * sr[j / KK];
        sum += v * v;
    }
    #pragma unroll
    for (int o = 16; o > 0; o >>= 1) sum += __shfl_xor_sync(0xffffffffu, sum, o);
    __shared__ float red[4];
    if ((tid & 31) == 0) red[tid >> 5] = sum;
    __syncthreads();
    if (tid == 0) {
        float t = red[0] + red[1] + red[2] + red[3];
        g_d[b * COUT + co] = rsqrtf(t + 1e-8f);
    }
}

// ---------------------------------------------------------------------------
// 3) wmod: elementwise, coalesced read & write
// ---------------------------------------------------------------------------
__global__ void wmod_kernel(const float* __restrict__ weight) {
    int idx = blockIdx.x * 256 + threadIdx.x;
    const int total = B_ * COUT * CIN * KK;
    if (idx >= total) return;
    int j  = idx % (CIN * KK);
    int co = (idx / (CIN * KK)) % COUT;
    int b  = idx / (CIN * KK * COUT);
    int cin = j / KK;
    g_wmod[idx] = weight[co * (CIN * KK) + j] * g_s[b * CIN + cin] * g_d[b * COUT + co];
}

// ---------------------------------------------------------------------------
// 4) conv: block = (b, 64-cout tile, 16x16 spatial tile), 256 threads.
//    Thread: tx = tid&3 (cols tx+4c), ty = (tid>>2)&7 (rows 2ty+r),
//            tc = tid>>5 (couts tc+8i, uniform per warp -> smem broadcast).
//    Cin chunk = 8. x smem pitch 18 => x LDS conflict-free (4ty+tx covers
//    all 32 banks). w smem [tap][cout] pitch 65, read uniform per warp.
// ---------------------------------------------------------------------------
#define CC 8
__global__ __launch_bounds__(256, 2)
void conv_kernel(const float* __restrict__ x,
                 const float* __restrict__ noise,
                 const float* __restrict__ bias,
                 float* __restrict__ out) {
    __shared__ float xs[CC][18][18];       // 10368 B
    __shared__ float ws[CC * KK][65];      // 18720 B

    const int b    = blockIdx.z;
    const int cob  = blockIdx.y * 64;
    const int tileY = (blockIdx.x >> 2) * 16;
    const int tileX = (blockIdx.x & 3) * 16;
    const int tid = threadIdx.x;
    const int tx = tid & 3;
    const int ty = (tid >> 2) & 7;
    const int tc = tid >> 5;

    float acc[8][2][4];
    #pragma unroll
    for (int i = 0; i < 8; i++)
        #pragma unroll
        for (int r = 0; r < 2; r++)
            #pragma unroll
            for (int c = 0; c < 4; c++) acc[i][r][c] = 0.f;

    const float* xb = x + (b * CIN) * (HW * HW);

    for (int cin0 = 0; cin0 < CIN; cin0 += CC) {
        // ---- load x tile (with halo, zero-padded) ----
        for (int i = tid; i < CC * 18 * 18; i += 256) {
            int cc  = i / 324;
            int rem = i - cc * 324;
            int ry  = rem / 18;
            int rx  = rem - ry * 18;
            int gy = tileY - 1 + ry;
            int gx = tileX - 1 + rx;
            float v = 0.f;
            if ((unsigned)gy < (unsigned)HW && (unsigned)gx < (unsigned)HW)
                v = xb[(cin0 + cc) * (HW * HW) + (gy << 6) + gx];
            xs[cc][ry][rx] = v;
        }
        // ---- load w tile: ws[j][co], j = cc*9+tap ----
        {
            const float* wbase = g_wmod + (b * COUT + cob) * (CIN * KK) + cin0 * KK;
            for (int i = tid; i < 64 * CC * KK; i += 256) {
                int co = i / (CC * KK);
                int j  = i - co * (CC * KK);
                ws[j][co] = wbase[co * (CIN * KK) + j];
            }
        }
        __syncthreads();

        // ---- compute ----
        for (int cc = 0; cc < CC; cc++) {
            #pragma unroll
            for (int kh = 0; kh < 3; kh++) {
                #pragma unroll
                for (int kw = 0; kw < 3; kw++) {
                    const int j = cc * KK + kh * 3 + kw;
                    float wv[8];
                    #pragma unroll
                    for (int i = 0; i < 8; i++) wv[i] = ws[j][tc + 8 * i];
                    float xv[2][4];
                    #pragma unroll
                    for (int r = 0; r < 2; r++)
                        #pragma unroll
                        for (int c = 0; c < 4; c++)
                            xv[r][c] = xs[cc][ty * 2 + r + kh][tx + 4 * c + kw];
                    #pragma unroll
                    for (int i = 0; i < 8; i++)
                        #pragma unroll
                        for (int r = 0; r < 2; r++)
                            #pragma unroll
                            for (int c = 0; c < 4; c++)
                                acc[i][r][c] = fmaf(wv[i], xv[r][c], acc[i][r][c]);
                }
            }
        }
        __syncthreads();
    }

    // ---- epilogue: + noise + bias, leaky relu 0.2 ----
    #pragma unroll
    for (int i = 0; i < 8; i++) {
        const int co = cob + tc + 8 * i;
        const float bi = bias[co];
        #pragma unroll
        for (int r = 0; r < 2; r++) {
            const int oy = tileY + ty * 2 + r;
            #pragma unroll
            for (int c = 0; c < 4; c++) {
                const int ox = tileX + tx + 4 * c;
                int o = ((b * COUT + co) << 12) + (oy << 6) + ox;
                float v = acc[i][r][c] + noise[o] + bi;
                out[o] = (v >= 0.f) ? v : 0.2f * v;
            }
        }
    }
}

// ---------------------------------------------------------------------------
extern "C" void kernel_launch(void* const* d_in, const int* in_sizes, int n_in,
                              void* d_out, int out_size) {
    const float* x      = (const float*)d_in[0];  // [8,512,64,64]
    const float* w      = (const float*)d_in[1];  // [8,512]
    const float* noise  = (const float*)d_in[2];  // [8,512,64,64]
    const float* weight = (const float*)d_in[3];  // [1,512,512,3,3]
    const float* aw     = (const float*)d_in[4];  // [512,512]
    const float* ab     = (const float*)d_in[5];  // [512]
    const float* bias   = (const float*)d_in[6];  // [512]
    float* out = (float*)d_out;

    style_kernel<<<(B_ * CIN * 32 + 255) / 256, 256>>>(w, aw, ab);
    demod_kernel<<<dim3(COUT, B_), 128>>>(weight);
    {
        const int total = B_ * COUT * CIN * KK;
        wmod_kernel<<<(total + 255) / 256, 256>>>(weight);
    }
    conv_kernel<<<dim3(16, 8, B_), 256>>>(x, noise, bias, out);
}

// round 2
// speedup vs baseline: 1.2753x; 1.2753x over previous
#include <cuda_runtime.h>

// ---------------------------------------------------------------------------
// ModulatedConv2d (StyleGAN2-style) on GB300 — Round 2: packed f32x2 FMA
//   B=8, Cin=512, Cout=512, k=3, H=W=64, WDIM=512
// ---------------------------------------------------------------------------

#define B_    8
#define CIN   512
#define COUT  512
#define HW    64
#define WDIM  512
#define KK    9

typedef unsigned long long u64;

__device__ __forceinline__ u64 pack2(float a, float b) {
    u64 r; asm("mov.b64 %0, {%1, %2};" : "=l"(r) : "f"(a), "f"(b)); return r;
}
__device__ __forceinline__ void unpack2(u64 v, float& a, float& b) {
    asm("mov.b64 {%0, %1}, %2;" : "=f"(a), "=f"(b) : "l"(v));
}
__device__ __forceinline__ void ffma2(u64& d, u64 a, u64 b) {
    asm("fma.rn.f32x2 %0, %1, %2, %0;" : "+l"(d) : "l"(a), "l"(b));
}

// Scratch (allocation-free rule: __device__ globals)
__device__ float g_s[B_ * CIN];
__device__ float g_d[B_ * COUT];
__device__ float g_wmod[B_ * COUT * CIN * KK];   // 75.5 MB

// ---------------------------------------------------------------------------
__global__ void style_kernel(const float* __restrict__ w,
                             const float* __restrict__ aw,
                             const float* __restrict__ ab) {
    int gwarp = (blockIdx.x * blockDim.x + threadIdx.x) >> 5;
    int lane  = threadIdx.x & 31;
    if (gwarp >= B_ * CIN) return;
    int b = gwarp / CIN;
    int c = gwarp % CIN;
    const float* wr = w  + b * WDIM;
    const float* ar = aw + c * WDIM;
    float sum = 0.f;
    #pragma unroll 4
    for (int k = lane; k < WDIM; k += 32) sum += wr[k] * ar[k];
    #pragma unroll
    for (int o = 16; o > 0; o >>= 1) sum += __shfl_xor_sync(0xffffffffu, sum, o);
    if (lane == 0) g_s[gwarp] = sum + ab[c] + 1.0f;
}

// ---------------------------------------------------------------------------
__global__ void demod_kernel(const float* __restrict__ weight) {
    int co = blockIdx.x;
    int b  = blockIdx.y;
    int tid = threadIdx.x;
    const float* wr = weight + co * (CIN * KK);
    const float* sr = g_s + b * CIN;
    float sum = 0.f;
    for (int j = tid; j < CIN * KK; j += 128) {
        float v = wr[j] * sr[j / KK];
        sum += v * v;
    }
    #pragma unroll
    for (int o = 16; o > 0; o >>= 1) sum += __shfl_xor_sync(0xffffffffu, sum, o);
    __shared__ float red[4];
    if ((tid & 31) == 0) red[tid >> 5] = sum;
    __syncthreads();
    if (tid == 0) {
        float t = red[0] + red[1] + red[2] + red[3];
        g_d[b * COUT + co] = rsqrtf(t + 1e-8f);
    }
}

// ---------------------------------------------------------------------------
__global__ void wmod_kernel(const float* __restrict__ weight) {
    int idx = blockIdx.x * 256 + threadIdx.x;
    const int total = B_ * COUT * CIN * KK;
    if (idx >= total) return;
    int j  = idx % (CIN * KK);
    int co = (idx / (CIN * KK)) % COUT;
    int b  = idx / (CIN * KK * COUT);
    int cin = j / KK;
    g_wmod[idx] = weight[co * (CIN * KK) + j] * g_s[b * CIN + cin] * g_d[b * COUT + co];
}

// ---------------------------------------------------------------------------
// conv: block = (b, 64-cout tile, 16x16 spatial tile), 256 threads.
//   tx = tid&3 (cols tx+4c), ty = (tid>>2)&7 (rows 2ty+r), tc = tid>>5.
//   Thread accumulates 8 couts (tc+8i) x 2 rows x 4 cols, with cout pairs
//   (i=2p, 2p+1) packed into one f32x2 accumulator.
//   w smem layout permuted: ws[j][tc*8 + i] holds cout (cob + tc + 8i), so
//   each thread reads its cout pair with one LDS.64 (uniform per warp).
// ---------------------------------------------------------------------------
#define CC 8
__global__ __launch_bounds__(256, 2)
void conv_kernel(const float* __restrict__ x,
                 const float* __restrict__ noise,
                 const float* __restrict__ bias,
                 float* __restrict__ out) {
    __shared__ float xs[CC][18][18];        // 10368 B
    __shared__ float ws[CC * KK][66];       // 19008 B, rows 8B-aligned (264 B)

    const int b     = blockIdx.z;
    const int cob   = blockIdx.y * 64;
    const int tileY = (blockIdx.x >> 2) * 16;
    const int tileX = (blockIdx.x & 3) * 16;
    const int tid = threadIdx.x;
    const int tx = tid & 3;
    const int ty = (tid >> 2) & 7;
    const int tc = tid >> 5;

    u64 acc2[4][2][4];
    #pragma unroll
    for (int p = 0; p < 4; p++)
        #pragma unroll
        for (int r = 0; r < 2; r++)
            #pragma unroll
            for (int c = 0; c < 4; c++) acc2[p][r][c] = 0ull;

    const float* xb = x + (b * CIN) * (HW * HW);

    for (int cin0 = 0; cin0 < CIN; cin0 += CC) {
        // ---- load x tile (halo, zero-padded) ----
        for (int i = tid; i < CC * 18 * 18; i += 256) {
            int cc  = i / 324;
            int rem = i - cc * 324;
            int ry  = rem / 18;
            int rx  = rem - ry * 18;
            int gy = tileY - 1 + ry;
            int gx = tileX - 1 + rx;
            float v = 0.f;
            if ((unsigned)gy < (unsigned)HW && (unsigned)gx < (unsigned)HW)
                v = xb[(cin0 + cc) * (HW * HW) + (gy << 6) + gx];
            xs[cc][ry][rx] = v;
        }
        // ---- load w tile, permuted: ws[j][(co&7)*8 + (co>>3)] ----
        {
            const float* wbase = g_wmod + (b * COUT + cob) * (CIN * KK) + cin0 * KK;
            for (int i = tid; i < 64 * CC * KK; i += 256) {
                int co = i / (CC * KK);     // 0..63 local cout
                int j  = i - co * (CC * KK);
                int pos = ((co & 7) << 3) | (co >> 3);
                ws[j][pos] = wbase[co * (CIN * KK) + j];
            }
        }
        __syncthreads();

        // ---- compute ----
        #pragma unroll 1
        for (int cc = 0; cc < CC; cc++) {
            #pragma unroll
            for (int kh = 0; kh < 3; kh++) {
                #pragma unroll
                for (int kw = 0; kw < 3; kw++) {
                    const int j = cc * KK + kh * 3 + kw;
                    // 4 x LDS.64 of cout pairs (uniform per warp -> broadcast)
                    u64 wp[4];
                    const u64* wrow = (const u64*)&ws[j][tc << 3];
                    #pragma unroll
                    for (int p = 0; p < 4; p++) wp[p] = wrow[p];
                    // 8 x LDS.32 of x (conflict-free), broadcast-packed
                    u64 xp[2][4];
                    #pragma unroll
                    for (int r = 0; r < 2; r++)
                        #pragma unroll
                        for (int c = 0; c < 4; c++) {
                            float xv = xs[cc][ty * 2 + r + kh][tx + 4 * c + kw];
                            xp[r][c] = pack2(xv, xv);
                        }
                    #pragma unroll
                    for (int p = 0; p < 4; p++)
                        #pragma unroll
                        for (int r = 0; r < 2; r++)
                            #pragma unroll
                            for (int c = 0; c < 4; c++)
                                ffma2(acc2[p][r][c], wp[p], xp[r][c]);
                }
            }
        }
        __syncthreads();
    }

    // ---- epilogue: + noise + bias, leaky relu 0.2 ----
    #pragma unroll
    for (int p = 0; p < 4; p++) {
        const int coA = cob + tc + 16 * p;      // i = 2p
        const int coB = coA + 8;                // i = 2p+1
        const float bA = bias[coA];
        const float bB = bias[coB];
        #pragma unroll
        for (int r = 0; r < 2; r++) {
            const int oy = tileY + ty * 2 + r;
            #pragma unroll
            for (int c = 0; c < 4; c++) {
                const int ox = tileX + tx + 4 * c;
                float vA, vB;
                unpack2(acc2[p][r][c], vA, vB);
                int oA = ((b * COUT + coA) << 12) + (oy << 6) + ox;
                int oB = ((b * COUT + coB) << 12) + (oy << 6) + ox;
                float yA = vA + noise[oA] + bA;
                float yB = vB + noise[oB] + bB;
                out[oA] = (yA >= 0.f) ? yA : 0.2f * yA;
                out[oB] = (yB >= 0.f) ? yB : 0.2f * yB;
            }
        }
    }
}

// ---------------------------------------------------------------------------
extern "C" void kernel_launch(void* const* d_in, const int* in_sizes, int n_in,
                              void* d_out, int out_size) {
    const float* x      = (const float*)d_in[0];
    const float* w      = (const float*)d_in[1];
    const float* noise  = (const float*)d_in[2];
    const float* weight = (const float*)d_in[3];
    const float* aw     = (const float*)d_in[4];
    const float* ab     = (const float*)d_in[5];
    const float* bias   = (const float*)d_in[6];
    float* out = (float*)d_out;

    style_kernel<<<(B_ * CIN * 32 + 255) / 256, 256>>>(w, aw, ab);
    demod_kernel<<<dim3(COUT, B_), 128>>>(weight);
    {
        const int total = B_ * COUT * CIN * KK;
        wmod_kernel<<<(total + 255) / 256, 256>>>(weight);
    }
    conv_kernel<<<dim3(16, 8, B_), 256>>>(x, noise, bias, out);
}

// round 4
// speedup vs baseline: 2.7190x; 2.1320x over previous
#include <cuda_runtime.h>
#include <cuda_bf16.h>
#include <cstdint>

// ===========================================================================
// ModulatedConv2d on GB300 — Round 4: mma.sync (HMMA) implicit-GEMM conv
//   (tcgen05 unavailable: harness compiles via compute_103, no 'a' features)
//   For each tap: D[cout,px] += Wtap[cout,cin] * Xshift[cin,px]
//   fp32 ~= bf16 hi/lo: w*x ~= whi*xhi + whi*xlo + wlo*xhi
// ===========================================================================

#define B_    8
#define CIN   512
#define COUT  512
#define HW    64
#define WDIM  512

// ---- device scratch (allocation-free rule) ----
__device__ float g_s[B_ * CIN];
__device__ float g_d[B_ * COUT];
// W split: [b][tap][cout][cin] bf16 (cin contiguous)
__device__ __align__(16) __nv_bfloat16 g_whi[B_ * 9 * COUT * CIN];
__device__ __align__(16) __nv_bfloat16 g_wlo[B_ * 9 * COUT * CIN];
// X split transposed: [b][y][x][cin] bf16 (cin contiguous)
__device__ __align__(16) __nv_bfloat16 g_xhi[B_ * HW * HW * CIN];
__device__ __align__(16) __nv_bfloat16 g_xlo[B_ * HW * HW * CIN];

// ---------------------------------------------------------------------------
// PTX helpers (all sm_80-era, valid on compute_103)
// ---------------------------------------------------------------------------
__device__ __forceinline__ uint32_t smem_u32(const void* p) {
    uint32_t a;
    asm("{ .reg .u64 t; cvta.to.shared.u64 t, %1; cvt.u32.u64 %0, t; }" : "=r"(a) : "l"(p));
    return a;
}
__device__ __forceinline__ void cp16(uint32_t dst, const void* src, uint32_t n) {
    asm volatile("cp.async.cg.shared.global [%0], [%1], 16, %2;"
                 :: "r"(dst), "l"(src), "r"(n) : "memory");
}
__device__ __forceinline__ void cp_commit() {
    asm volatile("cp.async.commit_group;" ::: "memory");
}
template <int N> __device__ __forceinline__ void cp_wait() {
    asm volatile("cp.async.wait_group %0;" :: "n"(N) : "memory");
}
__device__ __forceinline__ void ldmx4(uint32_t a[4], uint32_t addr) {
    asm volatile("ldmatrix.sync.aligned.m8n8.x4.shared.b16 {%0,%1,%2,%3}, [%4];"
                 : "=r"(a[0]), "=r"(a[1]), "=r"(a[2]), "=r"(a[3]) : "r"(addr));
}
__device__ __forceinline__ void mma16816(float c[4], const uint32_t a[4],
                                         uint32_t b0, uint32_t b1) {
    asm volatile("mma.sync.aligned.m16n8k16.row.col.f32.bf16.bf16.f32 "
                 "{%0,%1,%2,%3}, {%4,%5,%6,%7}, {%8,%9}, {%0,%1,%2,%3};"
                 : "+f"(c[0]), "+f"(c[1]), "+f"(c[2]), "+f"(c[3])
                 : "r"(a[0]), "r"(a[1]), "r"(a[2]), "r"(a[3]), "r"(b0), "r"(b1));
}

// ---------------------------------------------------------------------------
// Pre-kernels
// ---------------------------------------------------------------------------
__global__ void style_kernel(const float* __restrict__ w,
                             const float* __restrict__ aw,
                             const float* __restrict__ ab) {
    int gwarp = (blockIdx.x * blockDim.x + threadIdx.x) >> 5;
    int lane  = threadIdx.x & 31;
    if (gwarp >= B_ * CIN) return;
    int b = gwarp / CIN, c = gwarp % CIN;
    const float* wr = w + b * WDIM;
    const float* ar = aw + c * WDIM;
    float sum = 0.f;
    #pragma unroll 4
    for (int k = lane; k < WDIM; k += 32) sum += wr[k] * ar[k];
    #pragma unroll
    for (int o = 16; o > 0; o >>= 1) sum += __shfl_xor_sync(0xffffffffu, sum, o);
    if (lane == 0) g_s[gwarp] = sum + ab[c] + 1.0f;
}

__global__ void demod_kernel(const float* __restrict__ weight) {
    int co = blockIdx.x, b = blockIdx.y, tid = threadIdx.x;
    const float* wr = weight + co * (CIN * 9);
    const float* sr = g_s + b * CIN;
    float sum = 0.f;
    for (int j = tid; j < CIN * 9; j += 128) {
        float v = wr[j] * sr[j / 9];
        sum += v * v;
    }
    #pragma unroll
    for (int o = 16; o > 0; o >>= 1) sum += __shfl_xor_sync(0xffffffffu, sum, o);
    __shared__ float red[4];
    if ((tid & 31) == 0) red[tid >> 5] = sum;
    __syncthreads();
    if (tid == 0)
        g_d[b * COUT + co] = rsqrtf(red[0] + red[1] + red[2] + red[3] + 1e-8f);
}

// W split: block = cout, thread = cin
__global__ void wsplit_kernel(const float* __restrict__ weight) {
    int co = blockIdx.x, ci = threadIdx.x;
    float w9[9];
    #pragma unroll
    for (int t = 0; t < 9; t++) w9[t] = weight[(co * CIN + ci) * 9 + t];
    #pragma unroll
    for (int b = 0; b < B_; b++) {
        float sd = g_s[b * CIN + ci] * g_d[b * COUT + co];
        #pragma unroll
        for (int t = 0; t < 9; t++) {
            float v = w9[t] * sd;
            __nv_bfloat16 hi = __float2bfloat16_rn(v);
            __nv_bfloat16 lo = __float2bfloat16_rn(v - __bfloat162float(hi));
            int idx = (((b * 9 + t) * COUT) + co) * CIN + ci;
            g_whi[idx] = hi;
            g_wlo[idx] = lo;
        }
    }
}

// X split + transpose to [b][y][x][cin], via smem tiles
__global__ void xsplitT_kernel(const float* __restrict__ x) {
    __shared__ __nv_bfloat16 shi[64][130];
    __shared__ __nv_bfloat16 slo[64][130];
    int y = blockIdx.x, b = blockIdx.y, tid = threadIdx.x;
    for (int c0 = 0; c0 < CIN; c0 += 128) {
        for (int i = tid; i < 64 * 128; i += 256) {
            int cc = i >> 6, xx = i & 63;
            float v = x[(((size_t)b * CIN + c0 + cc) * HW + y) * HW + xx];
            __nv_bfloat16 hi = __float2bfloat16_rn(v);
            __nv_bfloat16 lo = __float2bfloat16_rn(v - __bfloat162float(hi));
            shi[xx][cc] = hi;
            slo[xx][cc] = lo;
        }
        __syncthreads();
        for (int i = tid; i < 64 * 128; i += 256) {
            int xx = i >> 7, cc = i & 127;
            size_t o = (((size_t)b * HW + y) * HW + xx) * CIN + c0 + cc;
            g_xhi[o] = shi[xx][cc];
            g_xlo[o] = slo[xx][cc];
        }
        __syncthreads();
    }
}

// ---------------------------------------------------------------------------
// Main HMMA conv kernel
//   grid = (32 rowpairs, 4 couttiles, 8 b), 256 threads (8 warps 2x4)
//   CTA tile: 128 cout x 128 px (2 rows). K loop: 32 chunks of 16 cin,
//   9 taps inner. Double-buffered cp.async.
// smem layout (bytes):
//   W: [stage][hi/lo][tap(9)][co(128)][16 cin]  stage=73728, hl=36864
//   X: [stage][hi/lo][pos(264=4x66)][24 hw pad] stage=25344, hl=12672
// ---------------------------------------------------------------------------
#define WS_STAGE 73728
#define WS_HL    36864
#define XS_BASE  147456
#define XS_STAGE 25344
#define XS_HL    12672
#define SMEM_TOTAL 198144

__global__ __launch_bounds__(256, 1)
void conv_hmma(const float* __restrict__ noise,
               const float* __restrict__ bias,
               float* __restrict__ out) {
    extern __shared__ __align__(128) char sm[];
    const uint32_t smb = smem_u32(sm);
    const int tid = threadIdx.x, lane = tid & 31, wid = tid >> 5;
    const int y0 = blockIdx.x * 2, cob = blockIdx.y * 128, b = blockIdx.z;
    const int wm = wid >> 2, wn = wid & 3;    // warp: 64 cout x 32 px
    const int g = lane >> 2, t = lane & 3;

    float acc[4][4][4];
    #pragma unroll
    for (int mf = 0; mf < 4; mf++)
        #pragma unroll
        for (int nf = 0; nf < 4; nf++)
            #pragma unroll
            for (int k = 0; k < 4; k++) acc[mf][nf][k] = 0.f;

    // per-lane ldmatrix offset inside one tap's [128][32B] block
    const uint32_t lmoff = (uint32_t)((lane & 15) * 32 + ((lane >> 4) & 1) * 16);

    auto load_chunk = [&](int cin0, int s) {
        // W: 9 taps x 128 couts x 32B, hi+lo  (4608 cp.async)
        const uint32_t wb = smb + s * WS_STAGE;
        for (int i = tid; i < 4608; i += 256) {
            int hl = i & 1;
            int j  = i >> 1;              // 0..2303
            int co = j & 127;
            int k2 = j >> 7;              // 0..17
            int tap = k2 % 9;
            int hl2 = k2 / 9;             // 0=hi 1=lo
            const __nv_bfloat16* src = (hl2 ? g_wlo : g_whi)
                + ((size_t)((b * 9 + tap) * COUT + cob + co)) * CIN + cin0 + hl * 8;
            cp16(wb + hl2 * WS_HL + tap * 4096 + co * 32 + hl * 16, src, 16);
        }
        // X halo: 4 rows x 66 cols x 32B, hi+lo, zero-fill OOB (1056 cp.async)
        const uint32_t xb = smb + XS_BASE + s * XS_STAGE;
        for (int i = tid; i < 1056; i += 256) {
            int hl  = i & 1;
            int j   = i >> 1;             // 0..527
            int pos = j % 264;
            int hl2 = j / 264;
            int hy = pos / 66;
            int hx = pos - hy * 66;
            int gy = y0 - 1 + hy;
            int gx = hx - 1;
            bool ok = ((unsigned)gy < 64u) && ((unsigned)gx < 64u);
            int gyc = ok ? gy : 0, gxc = ok ? gx : 0;
            const __nv_bfloat16* src = (hl2 ? g_xlo : g_xhi)
                + ((size_t)((b * HW + gyc) * HW + gxc)) * CIN + cin0 + hl * 8;
            cp16(xb + hl2 * XS_HL + pos * 48 + hl * 16, src, ok ? 16u : 0u);
        }
    };

    load_chunk(0, 0);
    cp_commit();

    for (int c = 0; c < 32; c++) {
        const int s = c & 1;
        if (c < 31) { load_chunk((c + 1) << 4, s ^ 1); cp_commit(); cp_wait<1>(); }
        else        { cp_wait<0>(); }
        __syncthreads();

        const uint32_t wh = smb + s * WS_STAGE;
        const uint32_t wl = wh + WS_HL;
        const char* xhp = sm + XS_BASE + s * XS_STAGE;
        const char* xlp = xhp + XS_HL;

        #pragma unroll 1
        for (int tap = 0; tap < 9; tap++) {
            const int dy = tap / 3, dx = tap - dy * 3;
            uint32_t Ahi[4][4], Alo[4][4];
            #pragma unroll
            for (int mf = 0; mf < 4; mf++) {
                const uint32_t rowb = (uint32_t)((wm * 64 + mf * 16) * 32);
                ldmx4(Ahi[mf], wh + tap * 4096 + rowb + lmoff);
                ldmx4(Alo[mf], wl + tap * 4096 + rowb + lmoff);
            }
            #pragma unroll
            for (int nf = 0; nf < 4; nf++) {
                const int pxb = wn * 32 + nf * 8;
                const int ph = ((pxb >> 6) + dy) * 66 + (pxb & 63) + dx + g;
                const int off = ph * 48 + t * 4;
                const uint32_t bh0 = *(const uint32_t*)(xhp + off);
                const uint32_t bh1 = *(const uint32_t*)(xhp + off + 16);
                const uint32_t bl0 = *(const uint32_t*)(xlp + off);
                const uint32_t bl1 = *(const uint32_t*)(xlp + off + 16);
                #pragma unroll
                for (int mf = 0; mf < 4; mf++) {
                    mma16816(acc[mf][nf], Ahi[mf], bh0, bh1);
                    mma16816(acc[mf][nf], Ahi[mf], bl0, bl1);
                    mma16816(acc[mf][nf], Alo[mf], bh0, bh1);
                }
            }
        }
        __syncthreads();
    }

    // ---- epilogue: + noise + bias, leaky 0.2, float2 stores ----
    #pragma unroll
    for (int mf = 0; mf < 4; mf++) {
        const int co = cob + wm * 64 + mf * 16 + g;
        const float bi0 = bias[co];
        const float bi8 = bias[co + 8];
        #pragma unroll
        for (int nf = 0; nf < 4; nf++) {
            const int px = wn * 32 + nf * 8 + 2 * t;
            const int y  = y0 + (px >> 6);
            const int xo = px & 63;
            const size_t o0 = (((size_t)(b * COUT + co)) * HW + y) * HW + xo;
            const size_t o1 = o0 + (size_t)8 * HW * HW;
            float2 n0 = *(const float2*)(noise + o0);
            float2 n1 = *(const float2*)(noise + o1);
            float v0 = acc[mf][nf][0] + n0.x + bi0;
            float v1 = acc[mf][nf][1] + n0.y + bi0;
            float v2 = acc[mf][nf][2] + n1.x + bi8;
            float v3 = acc[mf][nf][3] + n1.y + bi8;
            float2 r0, r1;
            r0.x = (v0 >= 0.f) ? v0 : 0.2f * v0;
            r0.y = (v1 >= 0.f) ? v1 : 0.2f * v1;
            r1.x = (v2 >= 0.f) ? v2 : 0.2f * v2;
            r1.y = (v3 >= 0.f) ? v3 : 0.2f * v3;
            *(float2*)(out + o0) = r0;
            *(float2*)(out + o1) = r1;
        }
    }
}

// ---------------------------------------------------------------------------
extern "C" void kernel_launch(void* const* d_in, const int* in_sizes, int n_in,
                              void* d_out, int out_size) {
    const float* x      = (const float*)d_in[0];
    const float* w      = (const float*)d_in[1];
    const float* noise  = (const float*)d_in[2];
    const float* weight = (const float*)d_in[3];
    const float* aw     = (const float*)d_in[4];
    const float* ab     = (const float*)d_in[5];
    const float* bias   = (const float*)d_in[6];
    float* out = (float*)d_out;

    cudaFuncSetAttribute(conv_hmma, cudaFuncAttributeMaxDynamicSharedMemorySize,
                         SMEM_TOTAL);

    style_kernel<<<(B_ * CIN * 32 + 255) / 256, 256>>>(w, aw, ab);
    demod_kernel<<<dim3(COUT, B_), 128>>>(weight);
    wsplit_kernel<<<COUT, CIN>>>(weight);
    xsplitT_kernel<<<dim3(HW, B_), 256>>>(x);
    conv_hmma<<<dim3(32, 4, B_), 256, SMEM_TOTAL>>>(noise, bias, out);
}

// round 5
// speedup vs baseline: 3.9931x; 1.4686x over previous
#include <cuda_runtime.h>
#include <cuda_fp16.h>
#include <cstdint>

// ===========================================================================
// ModulatedConv2d on GB300 — Round 5: fp16 2-term HMMA implicit-GEMM conv
//   tap loop: D[cout,px] += Wtap[cout,cin] * Xshift[cin,px]
//   fp32 ~= fp16: w*x ~= whi*xhi + whi*xlo   (error ~ wlo*x ~ 2^-11, random)
//   CTA: 128 cout x 256 px (4 rows), 512 threads, 3-stage cp.async pipeline
// ===========================================================================

#define B_    8
#define CIN   512
#define COUT  512
#define HW    64
#define WDIM  512

// ---- device scratch ----
__device__ float g_s[B_ * CIN];
__device__ float g_d[B_ * COUT];
// W: [b][tap][cout][cin] fp16 (cin contiguous)
__device__ __align__(16) __half g_wh[B_ * 9 * COUT * CIN];
// X hi/lo: [b][y][x][cin] fp16 (cin contiguous)
__device__ __align__(16) __half g_xh[B_ * HW * HW * CIN];
__device__ __align__(16) __half g_xl[B_ * HW * HW * CIN];

// ---------------------------------------------------------------------------
__device__ __forceinline__ uint32_t smem_u32(const void* p) {
    uint32_t a;
    asm("{ .reg .u64 t; cvta.to.shared.u64 t, %1; cvt.u32.u64 %0, t; }" : "=r"(a) : "l"(p));
    return a;
}
__device__ __forceinline__ void cp16(uint32_t dst, const void* src, uint32_t n) {
    asm volatile("cp.async.cg.shared.global [%0], [%1], 16, %2;"
                 :: "r"(dst), "l"(src), "r"(n) : "memory");
}
__device__ __forceinline__ void cp_commit() {
    asm volatile("cp.async.commit_group;" ::: "memory");
}
template <int N> __device__ __forceinline__ void cp_wait() {
    asm volatile("cp.async.wait_group %0;" :: "n"(N) : "memory");
}
__device__ __forceinline__ void ldmx4(uint32_t a[4], uint32_t addr) {
    asm volatile("ldmatrix.sync.aligned.m8n8.x4.shared.b16 {%0,%1,%2,%3}, [%4];"
                 : "=r"(a[0]), "=r"(a[1]), "=r"(a[2]), "=r"(a[3]) : "r"(addr));
}
__device__ __forceinline__ void mma16816(float c[4], const uint32_t a[4],
                                         uint32_t b0, uint32_t b1) {
    asm volatile("mma.sync.aligned.m16n8k16.row.col.f32.f16.f16.f32 "
                 "{%0,%1,%2,%3}, {%4,%5,%6,%7}, {%8,%9}, {%0,%1,%2,%3};"
                 : "+f"(c[0]), "+f"(c[1]), "+f"(c[2]), "+f"(c[3])
                 : "r"(a[0]), "r"(a[1]), "r"(a[2]), "r"(a[3]), "r"(b0), "r"(b1));
}

// ---------------------------------------------------------------------------
// Pre-kernels
// ---------------------------------------------------------------------------
__global__ void style_kernel(const float* __restrict__ w,
                             const float* __restrict__ aw,
                             const float* __restrict__ ab) {
    int gwarp = (blockIdx.x * blockDim.x + threadIdx.x) >> 5;
    int lane  = threadIdx.x & 31;
    if (gwarp >= B_ * CIN) return;
    int b = gwarp / CIN, c = gwarp % CIN;
    const float* wr = w + b * WDIM;
    const float* ar = aw + c * WDIM;
    float sum = 0.f;
    #pragma unroll 4
    for (int k = lane; k < WDIM; k += 32) sum += wr[k] * ar[k];
    #pragma unroll
    for (int o = 16; o > 0; o >>= 1) sum += __shfl_xor_sync(0xffffffffu, sum, o);
    if (lane == 0) g_s[gwarp] = sum + ab[c] + 1.0f;
}

__global__ void demod_kernel(const float* __restrict__ weight) {
    int co = blockIdx.x, b = blockIdx.y, tid = threadIdx.x;
    const float* wr = weight + co * (CIN * 9);
    const float* sr = g_s + b * CIN;
    float sum = 0.f;
    for (int j = tid; j < CIN * 9; j += 128) {
        float v = wr[j] * sr[j / 9];
        sum += v * v;
    }
    #pragma unroll
    for (int o = 16; o > 0; o >>= 1) sum += __shfl_xor_sync(0xffffffffu, sum, o);
    __shared__ float red[4];
    if ((tid & 31) == 0) red[tid >> 5] = sum;
    __syncthreads();
    if (tid == 0)
        g_d[b * COUT + co] = rsqrtf(red[0] + red[1] + red[2] + red[3] + 1e-8f);
}

// W modulate+quantize to fp16: block = cout, thread = cin
__global__ void wsplit_kernel(const float* __restrict__ weight) {
    int co = blockIdx.x, ci = threadIdx.x;
    float w9[9];
    #pragma unroll
    for (int t = 0; t < 9; t++) w9[t] = weight[(co * CIN + ci) * 9 + t];
    #pragma unroll
    for (int b = 0; b < B_; b++) {
        float sd = g_s[b * CIN + ci] * g_d[b * COUT + co];
        #pragma unroll
        for (int t = 0; t < 9; t++) {
            int idx = (((b * 9 + t) * COUT) + co) * CIN + ci;
            g_wh[idx] = __float2half_rn(w9[t] * sd);
        }
    }
}

// X split + transpose to [b][y][x][cin] fp16 hi/lo
__global__ void xsplitT_kernel(const float* __restrict__ x) {
    __shared__ __half shi[64][130];
    __shared__ __half slo[64][130];
    int y = blockIdx.x, b = blockIdx.y, tid = threadIdx.x;
    for (int c0 = 0; c0 < CIN; c0 += 128) {
        for (int i = tid; i < 64 * 128; i += 512) {
            int cc = i >> 6, xx = i & 63;
            float v = x[(((size_t)b * CIN + c0 + cc) * HW + y) * HW + xx];
            __half hi = __float2half_rn(v);
            __half lo = __float2half_rn(v - __half2float(hi));
            shi[xx][cc] = hi;
            slo[xx][cc] = lo;
        }
        __syncthreads();
        for (int i = tid; i < 64 * 64; i += 512) {
            int xx = i >> 6, cc = (i & 63) << 1;
            size_t o = (((size_t)b * HW + y) * HW + xx) * CIN + c0 + cc;
            *(uint32_t*)&g_xh[o] = *(const uint32_t*)&shi[xx][cc];
            *(uint32_t*)&g_xl[o] = *(const uint32_t*)&slo[xx][cc];
        }
        __syncthreads();
    }
}

// ---------------------------------------------------------------------------
// Main HMMA conv kernel
//   grid = (16 rowquads, 4 couttiles, 8 b), 512 threads (16 warps, 2m x 8n)
//   CTA tile: 128 cout x 256 px (4 rows). K: 32 chunks x 16 cin, 9 taps.
//   3-stage cp.async pipeline.
// smem per stage (74880 B):
//   W: [tap9][co128][32B]  (ldmatrix-swizzled)          36864 B
//   X: [hi/lo][pos 6x66][48B stride, 32B data]          38016 B
// ---------------------------------------------------------------------------
#define ST_BYTES 74880
#define XS_OFF   36864
#define XS_HL    19008
#define SMEM_TOTAL (3 * ST_BYTES)

__global__ __launch_bounds__(512, 1)
void conv_hmma(const float* __restrict__ noise,
               const float* __restrict__ bias,
               float* __restrict__ out) {
    extern __shared__ __align__(128) char sm[];
    const uint32_t smb = smem_u32(sm);
    const int tid = threadIdx.x, lane = tid & 31, wid = tid >> 5;
    const int y0 = blockIdx.x * 4, cob = blockIdx.y * 128, b = blockIdx.z;
    const int wm = wid >> 3, wn = wid & 7;    // warp: 64 cout x 32 px
    const int g = lane >> 2, t = lane & 3;

    float acc[4][4][4];
    #pragma unroll
    for (int mf = 0; mf < 4; mf++)
        #pragma unroll
        for (int nf = 0; nf < 4; nf++)
            #pragma unroll
            for (int k = 0; k < 4; k++) acc[mf][nf][k] = 0.f;

    // ldmatrix lane offset with phase-conflict-free swizzle:
    //   row r at r*32 bytes, 16B-half h stored at (h ^ ((r>>2)&1))
    const uint32_t lmoff = (uint32_t)((lane & 15) * 32 +
                           ((((lane >> 4) ^ (lane >> 2)) & 1) * 16));

    const __half* wgbase = g_wh + ((size_t)(b * 9) * COUT + cob) * CIN;
    const __half* xgh = g_xh + (size_t)b * (HW * HW * CIN);
    const __half* xgl = g_xl + (size_t)b * (HW * HW * CIN);

    auto load_chunk = [&](int cin0, int s) {
        const uint32_t wb = smb + s * ST_BYTES;
        // W: 9 taps x 128 co x 32B = 2304 x 16B
        for (int i = tid; i < 2304; i += 512) {
            int tap = i >> 8;
            int j   = i & 255;
            int co  = j >> 1;
            int h   = j & 1;
            const __half* src = wgbase + (size_t)tap * (COUT * CIN) + co * CIN + cin0 + h * 8;
            cp16(wb + tap * 4096 + co * 32 + ((h ^ ((co >> 2) & 1)) * 16), src, 16);
        }
        // X: hi/lo x 396 pos x 32B = 1584 x 16B, zero-fill OOB
        const uint32_t xb = wb + XS_OFF;
        for (int i = tid; i < 1584; i += 512) {
            int pos = i >> 2;
            int hl  = (i >> 1) & 1;
            int h2  = i & 1;
            int hy  = pos / 66;
            int hx  = pos - hy * 66;
            int gy = y0 - 1 + hy;
            int gx = hx - 1;
            bool ok = ((unsigned)gy < 64u) && ((unsigned)gx < 64u);
            int gyc = ok ? gy : 0, gxc = ok ? gx : 0;
            const __half* src = (hl ? xgl : xgh) + ((size_t)(gyc * 64 + gxc)) * CIN + cin0 + h2 * 8;
            cp16(xb + hl * XS_HL + pos * 48 + h2 * 16, src, ok ? 16u : 0u);
        }
    };

    load_chunk(0, 0);  cp_commit();
    load_chunk(16, 1); cp_commit();

    for (int c = 0; c < 32; c++) {
        const int s = c % 3;
        cp_wait<1>();
        __syncthreads();
        if (c + 2 < 32) load_chunk((c + 2) << 4, (c + 2) % 3);
        cp_commit();

        const uint32_t wsm = smb + s * ST_BYTES;
        const char* xhp = sm + s * ST_BYTES + XS_OFF;
        const char* xlp = xhp + XS_HL;

        #pragma unroll 1
        for (int tap = 0; tap < 9; tap++) {
            const int dy = tap / 3, dx = tap - dy * 3;
            uint32_t A[4][4];
            #pragma unroll
            for (int mf = 0; mf < 4; mf++)
                ldmx4(A[mf], wsm + tap * 4096 + (uint32_t)((wm * 64 + mf * 16) * 32) + lmoff);
            #pragma unroll
            for (int nf = 0; nf < 4; nf++) {
                const int pxb = wn * 32 + nf * 8;
                const int ph = ((pxb >> 6) + dy) * 66 + (pxb & 63) + dx + g;
                const int off = ph * 48 + t * 4;
                const uint32_t bh0 = *(const uint32_t*)(xhp + off);
                const uint32_t bh1 = *(const uint32_t*)(xhp + off + 16);
                const uint32_t bl0 = *(const uint32_t*)(xlp + off);
                const uint32_t bl1 = *(const uint32_t*)(xlp + off + 16);
                #pragma unroll
                for (int mf = 0; mf < 4; mf++) {
                    mma16816(acc[mf][nf], A[mf], bh0, bh1);
                    mma16816(acc[mf][nf], A[mf], bl0, bl1);
                }
            }
        }
    }

    // ---- epilogue: + noise + bias, leaky 0.2 ----
    #pragma unroll
    for (int mf = 0; mf < 4; mf++) {
        const int co = cob + wm * 64 + mf * 16 + g;
        const float bi0 = bias[co];
        const float bi8 = bias[co + 8];
        #pragma unroll
        for (int nf = 0; nf < 4; nf++) {
            const int px = wn * 32 + nf * 8 + 2 * t;
            const int y  = y0 + (px >> 6);
            const int xo = px & 63;
            const size_t o0 = (((size_t)(b * COUT + co)) * HW + y) * HW + xo;
            const size_t o1 = o0 + (size_t)8 * HW * HW;
            float2 n0 = *(const float2*)(noise + o0);
            float2 n1 = *(const float2*)(noise + o1);
            float v0 = acc[mf][nf][0] + n0.x + bi0;
            float v1 = acc[mf][nf][1] + n0.y + bi0;
            float v2 = acc[mf][nf][2] + n1.x + bi8;
            float v3 = acc[mf][nf][3] + n1.y + bi8;
            float2 r0, r1;
            r0.x = (v0 >= 0.f) ? v0 : 0.2f * v0;
            r0.y = (v1 >= 0.f) ? v1 : 0.2f * v1;
            r1.x = (v2 >= 0.f) ? v2 : 0.2f * v2;
            r1.y = (v3 >= 0.f) ? v3 : 0.2f * v3;
            *(float2*)(out + o0) = r0;
            *(float2*)(out + o1) = r1;
        }
    }
}

// ---------------------------------------------------------------------------
extern "C" void kernel_launch(void* const* d_in, const int* in_sizes, int n_in,
                              void* d_out, int out_size) {
    const float* x      = (const float*)d_in[0];
    const float* w      = (const float*)d_in[1];
    const float* noise  = (const float*)d_in[2];
    const float* weight = (const float*)d_in[3];
    const float* aw     = (const float*)d_in[4];
    const float* ab     = (const float*)d_in[5];
    const float* bias   = (const float*)d_in[6];
    float* out = (float*)d_out;

    cudaFuncSetAttribute(conv_hmma, cudaFuncAttributeMaxDynamicSharedMemorySize,
                         SMEM_TOTAL);

    style_kernel<<<(B_ * CIN * 32 + 255) / 256, 256>>>(w, aw, ab);
    demod_kernel<<<dim3(COUT, B_), 128>>>(weight);
    wsplit_kernel<<<COUT, CIN>>>(weight);
    xsplitT_kernel<<<dim3(HW, B_), 512>>>(x);
    conv_hmma<<<dim3(16, 4, B_), 512, SMEM_TOTAL>>>(noise, bias, out);
}

// round 6
// speedup vs baseline: 7.2859x; 1.8246x over previous
#include <cuda_runtime.h>
#include <cuda_fp16.h>
#include <cstdint>

// ===========================================================================
// ModulatedConv2d on GB300 — Round 6: 1-term fp16 HMMA implicit-GEMM conv
//   D[cout,px] += fp16(Wtap)[cout,cin] * fp16(X)shift[cin,px] per tap
//   (w-quant + x-quant errors each ~1.5e-4 after K-averaging; sum ~2e-4)
//   CTA: 128 cout x 128 px (2 rows), 256 thr, 2-stage cp.async, 2 CTA/SM
// ===========================================================================

#define B_    8
#define CIN   512
#define COUT  512
#define HW    64
#define WDIM  512

// ---- device scratch ----
__device__ float g_s[B_ * CIN];
__device__ float g_d[B_ * COUT];
// W: [b][tap][cout][cin] fp16 (cin contiguous)
__device__ __align__(16) __half g_wh[B_ * 9 * COUT * CIN];
// X: [b][y][x][cin] fp16 (cin contiguous)
__device__ __align__(16) __half g_xh[B_ * HW * HW * CIN];

// ---------------------------------------------------------------------------
__device__ __forceinline__ uint32_t smem_u32(const void* p) {
    uint32_t a;
    asm("{ .reg .u64 t; cvta.to.shared.u64 t, %1; cvt.u32.u64 %0, t; }" : "=r"(a) : "l"(p));
    return a;
}
__device__ __forceinline__ void cp16(uint32_t dst, const void* src, uint32_t n) {
    asm volatile("cp.async.cg.shared.global [%0], [%1], 16, %2;"
                 :: "r"(dst), "l"(src), "r"(n) : "memory");
}
__device__ __forceinline__ void cp_commit() {
    asm volatile("cp.async.commit_group;" ::: "memory");
}
template <int N> __device__ __forceinline__ void cp_wait() {
    asm volatile("cp.async.wait_group %0;" :: "n"(N) : "memory");
}
__device__ __forceinline__ void ldmx4(uint32_t a[4], uint32_t addr) {
    asm volatile("ldmatrix.sync.aligned.m8n8.x4.shared.b16 {%0,%1,%2,%3}, [%4];"
                 : "=r"(a[0]), "=r"(a[1]), "=r"(a[2]), "=r"(a[3]) : "r"(addr));
}
__device__ __forceinline__ void mma16816(float c[4], const uint32_t a[4],
                                         uint32_t b0, uint32_t b1) {
    asm volatile("mma.sync.aligned.m16n8k16.row.col.f32.f16.f16.f32 "
                 "{%0,%1,%2,%3}, {%4,%5,%6,%7}, {%8,%9}, {%0,%1,%2,%3};"
                 : "+f"(c[0]), "+f"(c[1]), "+f"(c[2]), "+f"(c[3])
                 : "r"(a[0]), "r"(a[1]), "r"(a[2]), "r"(a[3]), "r"(b0), "r"(b1));
}

// ---------------------------------------------------------------------------
// Pre-kernels
// ---------------------------------------------------------------------------
__global__ void style_kernel(const float* __restrict__ w,
                             const float* __restrict__ aw,
                             const float* __restrict__ ab) {
    int gwarp = (blockIdx.x * blockDim.x + threadIdx.x) >> 5;
    int lane  = threadIdx.x & 31;
    if (gwarp >= B_ * CIN) return;
    int b = gwarp / CIN, c = gwarp % CIN;
    const float* wr = w + b * WDIM;
    const float* ar = aw + c * WDIM;
    float sum = 0.f;
    #pragma unroll 4
    for (int k = lane; k < WDIM; k += 32) sum += wr[k] * ar[k];
    #pragma unroll
    for (int o = 16; o > 0; o >>= 1) sum += __shfl_xor_sync(0xffffffffu, sum, o);
    if (lane == 0) g_s[gwarp] = sum + ab[c] + 1.0f;
}

__global__ void demod_kernel(const float* __restrict__ weight) {
    int co = blockIdx.x, b = blockIdx.y, tid = threadIdx.x;
    const float* wr = weight + co * (CIN * 9);
    const float* sr = g_s + b * CIN;
    float sum = 0.f;
    for (int j = tid; j < CIN * 9; j += 128) {
        float v = wr[j] * sr[j / 9];
        sum += v * v;
    }
    #pragma unroll
    for (int o = 16; o > 0; o >>= 1) sum += __shfl_xor_sync(0xffffffffu, sum, o);
    __shared__ float red[4];
    if ((tid & 31) == 0) red[tid >> 5] = sum;
    __syncthreads();
    if (tid == 0)
        g_d[b * COUT + co] = rsqrtf(red[0] + red[1] + red[2] + red[3] + 1e-8f);
}

// W modulate + quantize to fp16: block = cout, thread = cin
__global__ void wsplit_kernel(const float* __restrict__ weight) {
    int co = blockIdx.x, ci = threadIdx.x;
    float w9[9];
    #pragma unroll
    for (int t = 0; t < 9; t++) w9[t] = weight[(co * CIN + ci) * 9 + t];
    #pragma unroll
    for (int b = 0; b < B_; b++) {
        float sd = g_s[b * CIN + ci] * g_d[b * COUT + co];
        #pragma unroll
        for (int t = 0; t < 9; t++) {
            int idx = (((b * 9 + t) * COUT) + co) * CIN + ci;
            g_wh[idx] = __float2half_rn(w9[t] * sd);
        }
    }
}

// X quantize + transpose to [b][y][x][cin] fp16
__global__ void xsplitT_kernel(const float* __restrict__ x) {
    __shared__ __half shi[64][130];
    int y = blockIdx.x, b = blockIdx.y, tid = threadIdx.x;
    for (int c0 = 0; c0 < CIN; c0 += 128) {
        for (int i = tid; i < 64 * 128; i += 512) {
            int cc = i >> 6, xx = i & 63;
            float v = x[(((size_t)b * CIN + c0 + cc) * HW + y) * HW + xx];
            shi[xx][cc] = __float2half_rn(v);
        }
        __syncthreads();
        for (int i = tid; i < 64 * 64; i += 512) {
            int xx = i >> 6, cc = (i & 63) << 1;
            size_t o = (((size_t)b * HW + y) * HW + xx) * CIN + c0 + cc;
            *(uint32_t*)&g_xh[o] = *(const uint32_t*)&shi[xx][cc];
        }
        __syncthreads();
    }
}

// ---------------------------------------------------------------------------
// Main HMMA conv kernel
//   grid = (32 rowpairs, 4 couttiles, 8 b) = 1024 CTAs
//   256 threads (8 warps, 2m x 4n), warp = 64 cout x 32 px
//   K: 32 chunks x 16 cin, 9 taps inner. 2-stage cp.async, 2 CTAs/SM.
// smem per stage (49536 B):
//   W: [tap9][co128][32B] (ldmatrix-swizzled)  36864 B
//   X: [pos 4x66][48B stride, 32B data]        12672 B
// ---------------------------------------------------------------------------
#define ST_BYTES 49536
#define XS_OFF   36864
#define SMEM_TOTAL (2 * ST_BYTES)

__global__ __launch_bounds__(256, 2)
void conv_hmma(const float* __restrict__ noise,
               const float* __restrict__ bias,
               float* __restrict__ out) {
    extern __shared__ __align__(128) char sm[];
    const uint32_t smb = smem_u32(sm);
    const int tid = threadIdx.x, lane = tid & 31, wid = tid >> 5;
    const int y0 = blockIdx.x * 2, cob = blockIdx.y * 128, b = blockIdx.z;
    const int wm = wid >> 2, wn = wid & 3;    // warp: 64 cout x 32 px
    const int g = lane >> 2, t = lane & 3;

    float acc[4][4][4];
    #pragma unroll
    for (int mf = 0; mf < 4; mf++)
        #pragma unroll
        for (int nf = 0; nf < 4; nf++)
            #pragma unroll
            for (int k = 0; k < 4; k++) acc[mf][nf][k] = 0.f;

    // ldmatrix lane offset; 16B-half h stored at (h ^ ((row>>2)&1))
    const uint32_t lmoff = (uint32_t)((lane & 15) * 32 +
                           ((((lane >> 4) ^ (lane >> 2)) & 1) * 16));

    const __half* wgbase = g_wh + ((size_t)(b * 9) * COUT + cob) * CIN;
    const __half* xgh = g_xh + (size_t)b * (HW * HW * CIN);

    auto load_chunk = [&](int cin0, int s) {
        const uint32_t wb = smb + s * ST_BYTES;
        // W: 9 taps x 128 co x 2 halves = 2304 x 16B
        for (int i = tid; i < 2304; i += 256) {
            int tap = i >> 8;
            int j   = i & 255;
            int co  = j >> 1;
            int h   = j & 1;
            const __half* src = wgbase + (size_t)tap * (COUT * CIN) + co * CIN + cin0 + h * 8;
            cp16(wb + tap * 4096 + co * 32 + ((h ^ ((co >> 2) & 1)) * 16), src, 16);
        }
        // X: 264 pos x 2 halves = 528 x 16B, zero-fill OOB
        const uint32_t xb = wb + XS_OFF;
        for (int i = tid; i < 528; i += 256) {
            int pos = i >> 1;
            int h2  = i & 1;
            int hy  = pos / 66;
            int hx  = pos - hy * 66;
            int gy = y0 - 1 + hy;
            int gx = hx - 1;
            bool ok = ((unsigned)gy < 64u) && ((unsigned)gx < 64u);
            int gyc = ok ? gy : 0, gxc = ok ? gx : 0;
            const __half* src = xgh + ((size_t)(gyc * 64 + gxc)) * CIN + cin0 + h2 * 8;
            cp16(xb + pos * 48 + h2 * 16, src, ok ? 16u : 0u);
        }
    };

    load_chunk(0, 0);
    cp_commit();

    for (int c = 0; c < 32; c++) {
        const int s = c & 1;
        if (c < 31) { load_chunk((c + 1) << 4, s ^ 1); cp_commit(); cp_wait<1>(); }
        else        { cp_wait<0>(); }
        __syncthreads();

        const uint32_t wsm = smb + s * ST_BYTES;
        const char* xhp = sm + s * ST_BYTES + XS_OFF;

        #pragma unroll 1
        for (int tap = 0; tap < 9; tap++) {
            const int dy = tap / 3, dx = tap - dy * 3;
            uint32_t A[4][4];
            #pragma unroll
            for (int mf = 0; mf < 4; mf++)
                ldmx4(A[mf], wsm + tap * 4096 + (uint32_t)((wm * 64 + mf * 16) * 32) + lmoff);
            #pragma unroll
            for (int nf = 0; nf < 4; nf++) {
                const int pxb = wn * 32 + nf * 8;
                const int ph = ((pxb >> 6) + dy) * 66 + (pxb & 63) + dx + g;
                const int off = ph * 48 + t * 4;
                const uint32_t bh0 = *(const uint32_t*)(xhp + off);
                const uint32_t bh1 = *(const uint32_t*)(xhp + off + 16);
                #pragma unroll
                for (int mf = 0; mf < 4; mf++)
                    mma16816(acc[mf][nf], A[mf], bh0, bh1);
            }
        }
        __syncthreads();
    }

    // ---- epilogue: + noise + bias, leaky 0.2 ----
    #pragma unroll
    for (int mf = 0; mf < 4; mf++) {
        const int co = cob + wm * 64 + mf * 16 + g;
        const float bi0 = bias[co];
        const float bi8 = bias[co + 8];
        #pragma unroll
        for (int nf = 0; nf < 4; nf++) {
            const int px = wn * 32 + nf * 8 + 2 * t;
            const int y  = y0 + (px >> 6);
            const int xo = px & 63;
            const size_t o0 = (((size_t)(b * COUT + co)) * HW + y) * HW + xo;
            const size_t o1 = o0 + (size_t)8 * HW * HW;
            float2 n0 = *(const float2*)(noise + o0);
            float2 n1 = *(const float2*)(noise + o1);
            float v0 = acc[mf][nf][0] + n0.x + bi0;
            float v1 = acc[mf][nf][1] + n0.y + bi0;
            float v2 = acc[mf][nf][2] + n1.x + bi8;
            float v3 = acc[mf][nf][3] + n1.y + bi8;
            float2 r0, r1;
            r0.x = (v0 >= 0.f) ? v0 : 0.2f * v0;
            r0.y = (v1 >= 0.f) ? v1 : 0.2f * v1;
            r1.x = (v2 >= 0.f) ? v2 : 0.2f * v2;
            r1.y = (v3 >= 0.f) ? v3 : 0.2f * v3;
            *(float2*)(out + o0) = r0;
            *(float2*)(out + o1) = r1;
        }
    }
}

// ---------------------------------------------------------------------------
extern "C" void kernel_launch(void* const* d_in, const int* in_sizes, int n_in,
                              void* d_out, int out_size) {
    const float* x      = (const float*)d_in[0];
    const float* w      = (const float*)d_in[1];
    const float* noise  = (const float*)d_in[2];
    const float* weight = (const float*)d_in[3];
    const float* aw     = (const float*)d_in[4];
    const float* ab     = (const float*)d_in[5];
    const float* bias   = (const float*)d_in[6];
    float* out = (float*)d_out;

    cudaFuncSetAttribute(conv_hmma, cudaFuncAttributeMaxDynamicSharedMemorySize,
                         SMEM_TOTAL);

    style_kernel<<<(B_ * CIN * 32 + 255) / 256, 256>>>(w, aw, ab);
    demod_kernel<<<dim3(COUT, B_), 128>>>(weight);
    wsplit_kernel<<<COUT, CIN>>>(weight);
    xsplitT_kernel<<<dim3(HW, B_), 512>>>(x);
    conv_hmma<<<dim3(32, 4, B_), 256, SMEM_TOTAL>>>(noise, bias, out);
}

// round 7
// speedup vs baseline: 7.8683x; 1.0799x over previous
#include <cuda_runtime.h>
#include <cuda_fp16.h>
#include <cstdint>

// ===========================================================================
// ModulatedConv2d on GB300 — Round 7: 1-term fp16 HMMA conv
//   + B-operand word-permuted X layout -> single LDS.64 per B frag
//   + X smem stride 32B (conflict-free, unpadded), tap loop unroll 3
// ===========================================================================

#define B_    8
#define CIN   512
#define COUT  512
#define HW    64
#define WDIM  512

// ---- device scratch ----
__device__ float g_s[B_ * CIN];
__device__ float g_d[B_ * COUT];
// W: [b][tap][cout][cin] fp16 (cin contiguous)
__device__ __align__(16) __half g_wh[B_ * 9 * COUT * CIN];
// X: [b][y][x][cin] fp16, each 16-cin group word-permuted [0,4,1,5,2,6,3,7]
__device__ __align__(16) __half g_xh[B_ * HW * HW * CIN];

// ---------------------------------------------------------------------------
__device__ __forceinline__ uint32_t smem_u32(const void* p) {
    uint32_t a;
    asm("{ .reg .u64 t; cvta.to.shared.u64 t, %1; cvt.u32.u64 %0, t; }" : "=r"(a) : "l"(p));
    return a;
}
__device__ __forceinline__ void cp16(uint32_t dst, const void* src, uint32_t n) {
    asm volatile("cp.async.cg.shared.global [%0], [%1], 16, %2;"
                 :: "r"(dst), "l"(src), "r"(n) : "memory");
}
__device__ __forceinline__ void cp_commit() {
    asm volatile("cp.async.commit_group;" ::: "memory");
}
template <int N> __device__ __forceinline__ void cp_wait() {
    asm volatile("cp.async.wait_group %0;" :: "n"(N) : "memory");
}
__device__ __forceinline__ void ldmx4(uint32_t a[4], uint32_t addr) {
    asm volatile("ldmatrix.sync.aligned.m8n8.x4.shared.b16 {%0,%1,%2,%3}, [%4];"
                 : "=r"(a[0]), "=r"(a[1]), "=r"(a[2]), "=r"(a[3]) : "r"(addr));
}
__device__ __forceinline__ void mma16816(float c[4], const uint32_t a[4],
                                         uint32_t b0, uint32_t b1) {
    asm volatile("mma.sync.aligned.m16n8k16.row.col.f32.f16.f16.f32 "
                 "{%0,%1,%2,%3}, {%4,%5,%6,%7}, {%8,%9}, {%0,%1,%2,%3};"
                 : "+f"(c[0]), "+f"(c[1]), "+f"(c[2]), "+f"(c[3])
                 : "r"(a[0]), "r"(a[1]), "r"(a[2]), "r"(a[3]), "r"(b0), "r"(b1));
}

// ---------------------------------------------------------------------------
// Pre-kernels
// ---------------------------------------------------------------------------
__global__ void style_kernel(const float* __restrict__ w,
                             const float* __restrict__ aw,
                             const float* __restrict__ ab) {
    int gwarp = (blockIdx.x * blockDim.x + threadIdx.x) >> 5;
    int lane  = threadIdx.x & 31;
    if (gwarp >= B_ * CIN) return;
    int b = gwarp / CIN, c = gwarp % CIN;
    const float* wr = w + b * WDIM;
    const float* ar = aw + c * WDIM;
    float sum = 0.f;
    #pragma unroll 4
    for (int k = lane; k < WDIM; k += 32) sum += wr[k] * ar[k];
    #pragma unroll
    for (int o = 16; o > 0; o >>= 1) sum += __shfl_xor_sync(0xffffffffu, sum, o);
    if (lane == 0) g_s[gwarp] = sum + ab[c] + 1.0f;
}

__global__ void demod_kernel(const float* __restrict__ weight) {
    int co = blockIdx.x, b = blockIdx.y, tid = threadIdx.x;
    const float* wr = weight + co * (CIN * 9);
    const float* sr = g_s + b * CIN;
    float sum = 0.f;
    for (int j = tid; j < CIN * 9; j += 128) {
        float v = wr[j] * sr[j / 9];
        sum += v * v;
    }
    #pragma unroll
    for (int o = 16; o > 0; o >>= 1) sum += __shfl_xor_sync(0xffffffffu, sum, o);
    __shared__ float red[4];
    if ((tid & 31) == 0) red[tid >> 5] = sum;
    __syncthreads();
    if (tid == 0)
        g_d[b * COUT + co] = rsqrtf(red[0] + red[1] + red[2] + red[3] + 1e-8f);
}

// W modulate + quantize to fp16: block = cout, thread = cin
__global__ void wsplit_kernel(const float* __restrict__ weight) {
    int co = blockIdx.x, ci = threadIdx.x;
    float w9[9];
    #pragma unroll
    for (int t = 0; t < 9; t++) w9[t] = weight[(co * CIN + ci) * 9 + t];
    #pragma unroll
    for (int b = 0; b < B_; b++) {
        float sd = g_s[b * CIN + ci] * g_d[b * COUT + co];
        #pragma unroll
        for (int t = 0; t < 9; t++) {
            int idx = (((b * 9 + t) * COUT) + co) * CIN + ci;
            g_wh[idx] = __float2half_rn(w9[t] * sd);
        }
    }
}

// X quantize + transpose to [b][y][x][cin] fp16, with per-16-group word
// permutation: word w (pair of halves) stored at position ((w&3)<<1)|(w>>2)
__global__ void xsplitT_kernel(const float* __restrict__ x) {
    __shared__ __half shi[64][130];
    int y = blockIdx.x, b = blockIdx.y, tid = threadIdx.x;
    for (int c0 = 0; c0 < CIN; c0 += 128) {
        for (int i = tid; i < 64 * 128; i += 512) {
            int cc = i >> 6, xx = i & 63;
            float v = x[(((size_t)b * CIN + c0 + cc) * HW + y) * HW + xx];
            shi[xx][cc] = __float2half_rn(v);
        }
        __syncthreads();
        for (int i = tid; i < 64 * 64; i += 512) {
            int xx = i >> 6;
            int wi = i & 63;                 // word index within 128 cin
            int cc = wi << 1;                // source halves (cc, cc+1)
            int w  = wi & 7;                 // word within 16-group
            int sp = ((w & 3) << 1) | (w >> 2);
            int ccp = (cc & ~15) | (sp << 1);
            size_t o = (((size_t)b * HW + y) * HW + xx) * CIN + c0 + ccp;
            *(uint32_t*)&g_xh[o] = *(const uint32_t*)&shi[xx][cc];
        }
        __syncthreads();
    }
}

// ---------------------------------------------------------------------------
// Main HMMA conv kernel
//   grid = (32 rowpairs, 4 couttiles, 8 b) = 1024 CTAs
//   256 threads (8 warps, 2m x 4n), warp = 64 cout x 32 px
//   K: 32 chunks x 16 cin, 9 taps inner. 2-stage cp.async, 2 CTAs/SM.
// smem per stage (45312 B):
//   W: [tap9][co128][32B] (ldmatrix-swizzled)   36864 B
//   X: [pos 4x66][32B, word-permuted]            8448 B
// ---------------------------------------------------------------------------
#define ST_BYTES 45312
#define XS_OFF   36864
#define SMEM_TOTAL (2 * ST_BYTES)

__global__ __launch_bounds__(256, 2)
void conv_hmma(const float* __restrict__ noise,
               const float* __restrict__ bias,
               float* __restrict__ out) {
    extern __shared__ __align__(128) char sm[];
    const uint32_t smb = smem_u32(sm);
    const int tid = threadIdx.x, lane = tid & 31, wid = tid >> 5;
    const int y0 = blockIdx.x * 2, cob = blockIdx.y * 128, b = blockIdx.z;
    const int wm = wid >> 2, wn = wid & 3;    // warp: 64 cout x 32 px
    const int g = lane >> 2, t = lane & 3;

    float acc[4][4][4];
    #pragma unroll
    for (int mf = 0; mf < 4; mf++)
        #pragma unroll
        for (int nf = 0; nf < 4; nf++)
            #pragma unroll
            for (int k = 0; k < 4; k++) acc[mf][nf][k] = 0.f;

    // ldmatrix lane offset; 16B-half h stored at (h ^ ((row>>2)&1))
    const uint32_t lmoff = (uint32_t)((lane & 15) * 32 +
                           ((((lane >> 4) ^ (lane >> 2)) & 1) * 16));

    const __half* wgbase = g_wh + ((size_t)(b * 9) * COUT + cob) * CIN;
    const __half* xgh = g_xh + (size_t)b * (HW * HW * CIN);

    auto load_chunk = [&](int cin0, int s) {
        const uint32_t wb = smb + s * ST_BYTES;
        // W: 9 taps x 128 co x 2 halves = 2304 x 16B
        for (int i = tid; i < 2304; i += 256) {
            int tap = i >> 8;
            int j   = i & 255;
            int co  = j >> 1;
            int h   = j & 1;
            const __half* src = wgbase + (size_t)tap * (COUT * CIN) + co * CIN + cin0 + h * 8;
            cp16(wb + tap * 4096 + co * 32 + ((h ^ ((co >> 2) & 1)) * 16), src, 16);
        }
        // X: 264 pos x 2 x 16B (contiguous 32B per pos), zero-fill OOB
        const uint32_t xb = wb + XS_OFF;
        for (int i = tid; i < 528; i += 256) {
            int pos = i >> 1;
            int h2  = i & 1;
            int hy  = pos / 66;
            int hx  = pos - hy * 66;
            int gy = y0 - 1 + hy;
            int gx = hx - 1;
            bool ok = ((unsigned)gy < 64u) && ((unsigned)gx < 64u);
            int gyc = ok ? gy : 0, gxc = ok ? gx : 0;
            const __half* src = xgh + ((size_t)(gyc * 64 + gxc)) * CIN + cin0 + h2 * 8;
            cp16(xb + pos * 32 + h2 * 16, src, ok ? 16u : 0u);
        }
    };

    load_chunk(0, 0);
    cp_commit();

    for (int c = 0; c < 32; c++) {
        const int s = c & 1;
        if (c < 31) { load_chunk((c + 1) << 4, s ^ 1); cp_commit(); cp_wait<1>(); }
        else        { cp_wait<0>(); }
        __syncthreads();

        const uint32_t wsm = smb + s * ST_BYTES;
        const char* xhp = sm + s * ST_BYTES + XS_OFF;

        #pragma unroll 3
        for (int tap = 0; tap < 9; tap++) {
            const int dy = tap / 3, dx = tap - dy * 3;
            uint32_t A[4][4];
            #pragma unroll
            for (int mf = 0; mf < 4; mf++)
                ldmx4(A[mf], wsm + tap * 4096 + (uint32_t)((wm * 64 + mf * 16) * 32) + lmoff);
            #pragma unroll
            for (int nf = 0; nf < 4; nf++) {
                const int pxb = wn * 32 + nf * 8;
                const int ph = ((pxb >> 6) + dy) * 66 + (pxb & 63) + dx + g;
                const uint2 bb = *(const uint2*)(xhp + ph * 32 + t * 8);
                #pragma unroll
                for (int mf = 0; mf < 4; mf++)
                    mma16816(acc[mf][nf], A[mf], bb.x, bb.y);
            }
        }
        __syncthreads();
    }

    // ---- epilogue: + noise + bias, leaky 0.2 ----
    #pragma unroll
    for (int mf = 0; mf < 4; mf++) {
        const int co = cob + wm * 64 + mf * 16 + g;
        const float bi0 = bias[co];
        const float bi8 = bias[co + 8];
        #pragma unroll
        for (int nf = 0; nf < 4; nf++) {
            const int px = wn * 32 + nf * 8 + 2 * t;
            const int y  = y0 + (px >> 6);
            const int xo = px & 63;
            const size_t o0 = (((size_t)(b * COUT + co)) * HW + y) * HW + xo;
            const size_t o1 = o0 + (size_t)8 * HW * HW;
            float2 n0 = *(const float2*)(noise + o0);
            float2 n1 = *(const float2*)(noise + o1);
            float v0 = acc[mf][nf][0] + n0.x + bi0;
            float v1 = acc[mf][nf][1] + n0.y + bi0;
            float v2 = acc[mf][nf][2] + n1.x + bi8;
            float v3 = acc[mf][nf][3] + n1.y + bi8;
            float2 r0, r1;
            r0.x = (v0 >= 0.f) ? v0 : 0.2f * v0;
            r0.y = (v1 >= 0.f) ? v1 : 0.2f * v1;
            r1.x = (v2 >= 0.f) ? v2 : 0.2f * v2;
            r1.y = (v3 >= 0.f) ? v3 : 0.2f * v3;
            *(float2*)(out + o0) = r0;
            *(float2*)(out + o1) = r1;
        }
    }
}

// ---------------------------------------------------------------------------
extern "C" void kernel_launch(void* const* d_in, const int* in_sizes, int n_in,
                              void* d_out, int out_size) {
    const float* x      = (const float*)d_in[0];
    const float* w      = (const float*)d_in[1];
    const float* noise  = (const float*)d_in[2];
    const float* weight = (const float*)d_in[3];
    const float* aw     = (const float*)d_in[4];
    const float* ab     = (const float*)d_in[5];
    const float* bias   = (const float*)d_in[6];
    float* out = (float*)d_out;

    cudaFuncSetAttribute(conv_hmma, cudaFuncAttributeMaxDynamicSharedMemorySize,
                         SMEM_TOTAL);

    style_kernel<<<(B_ * CIN * 32 + 255) / 256, 256>>>(w, aw, ab);
    demod_kernel<<<dim3(COUT, B_), 128>>>(weight);
    wsplit_kernel<<<COUT, CIN>>>(weight);
    xsplitT_kernel<<<dim3(HW, B_), 512>>>(x);
    conv_hmma<<<dim3(32, 4, B_), 256, SMEM_TOTAL>>>(noise, bias, out);
}

// round 8
// speedup vs baseline: 8.7240x; 1.1088x over previous
#include <cuda_runtime.h>
#include <cuda_fp16.h>
#include <cstdint>

// ===========================================================================
// ModulatedConv2d on GB300 — Round 8: 1-term fp16 HMMA conv
//   64co x 128px CTAs (128 thr), 4 CTAs/SM, 2048-CTA grid (1% tail)
//   demod fused into wsplit (weight read once)
// ===========================================================================

#define B_    8
#define CIN   512
#define COUT  512
#define HW    64
#define WDIM  512

// ---- device scratch ----
__device__ float g_s[B_ * CIN];
// W: [b][tap][cout][cin] fp16 (cin contiguous)
__device__ __align__(16) __half g_wh[B_ * 9 * COUT * CIN];
// X: [b][y][x][cin] fp16, each 16-cin group word-permuted [0,4,1,5,2,6,3,7]
__device__ __align__(16) __half g_xh[B_ * HW * HW * CIN];

// ---------------------------------------------------------------------------
__device__ __forceinline__ uint32_t smem_u32(const void* p) {
    uint32_t a;
    asm("{ .reg .u64 t; cvta.to.shared.u64 t, %1; cvt.u32.u64 %0, t; }" : "=r"(a) : "l"(p));
    return a;
}
__device__ __forceinline__ void cp16(uint32_t dst, const void* src, uint32_t n) {
    asm volatile("cp.async.cg.shared.global [%0], [%1], 16, %2;"
                 :: "r"(dst), "l"(src), "r"(n) : "memory");
}
__device__ __forceinline__ void cp_commit() {
    asm volatile("cp.async.commit_group;" ::: "memory");
}
template <int N> __device__ __forceinline__ void cp_wait() {
    asm volatile("cp.async.wait_group %0;" :: "n"(N) : "memory");
}
__device__ __forceinline__ void ldmx4(uint32_t a[4], uint32_t addr) {
    asm volatile("ldmatrix.sync.aligned.m8n8.x4.shared.b16 {%0,%1,%2,%3}, [%4];"
                 : "=r"(a[0]), "=r"(a[1]), "=r"(a[2]), "=r"(a[3]) : "r"(addr));
}
__device__ __forceinline__ void mma16816(float c[4], const uint32_t a[4],
                                         uint32_t b0, uint32_t b1) {
    asm volatile("mma.sync.aligned.m16n8k16.row.col.f32.f16.f16.f32 "
                 "{%0,%1,%2,%3}, {%4,%5,%6,%7}, {%8,%9}, {%0,%1,%2,%3};"
                 : "+f"(c[0]), "+f"(c[1]), "+f"(c[2]), "+f"(c[3])
                 : "r"(a[0]), "r"(a[1]), "r"(a[2]), "r"(a[3]), "r"(b0), "r"(b1));
}

// ---------------------------------------------------------------------------
// Pre-kernels
// ---------------------------------------------------------------------------
__global__ void style_kernel(const float* __restrict__ w,
                             const float* __restrict__ aw,
                             const float* __restrict__ ab) {
    int gwarp = (blockIdx.x * blockDim.x + threadIdx.x) >> 5;
    int lane  = threadIdx.x & 31;
    if (gwarp >= B_ * CIN) return;
    int b = gwarp / CIN, c = gwarp % CIN;
    const float* wr = w + b * WDIM;
    const float* ar = aw + c * WDIM;
    float sum = 0.f;
    #pragma unroll 4
    for (int k = lane; k < WDIM; k += 32) sum += wr[k] * ar[k];
    #pragma unroll
    for (int o = 16; o > 0; o >>= 1) sum += __shfl_xor_sync(0xffffffffu, sum, o);
    if (lane == 0) g_s[gwarp] = sum + ab[c] + 1.0f;
}

// W modulate + demod + quantize, weight read ONCE.
// block = cout (512 blocks), 512 threads = cin.
__global__ void wsplit_kernel(const float* __restrict__ weight) {
    __shared__ float red[16];
    __shared__ float dsh;
    const int co = blockIdx.x, ci = threadIdx.x;
    const int lane = ci & 31, wrp = ci >> 5;
    float w9[9];
    #pragma unroll
    for (int t = 0; t < 9; t++) w9[t] = weight[(co * CIN + ci) * 9 + t];
    #pragma unroll 1
    for (int b = 0; b < B_; b++) {
        const float sv = g_s[b * CIN + ci];
        float sum = 0.f;
        #pragma unroll
        for (int t = 0; t < 9; t++) { float v = w9[t] * sv; sum += v * v; }
        #pragma unroll
        for (int o = 16; o > 0; o >>= 1) sum += __shfl_xor_sync(0xffffffffu, sum, o);
        if (lane == 0) red[wrp] = sum;
        __syncthreads();
        if (ci < 16) {
            float v = red[ci];
            #pragma unroll
            for (int o = 8; o > 0; o >>= 1) v += __shfl_xor_sync(0xffffu, v, o, 16);
            if (ci == 0) dsh = rsqrtf(v + 1e-8f);
        }
        __syncthreads();
        const float sd = sv * dsh;
        #pragma unroll
        for (int t = 0; t < 9; t++) {
            int idx = (((b * 9 + t) * COUT) + co) * CIN + ci;
            g_wh[idx] = __float2half_rn(w9[t] * sd);
        }
        __syncthreads();
    }
}

// X quantize + transpose to [b][y][x][cin] fp16, word-permuted per 16-group
__global__ void xsplitT_kernel(const float* __restrict__ x) {
    __shared__ __half shi[64][130];
    int y = blockIdx.x, b = blockIdx.y, tid = threadIdx.x;
    for (int c0 = 0; c0 < CIN; c0 += 128) {
        for (int i = tid; i < 64 * 128; i += 512) {
            int cc = i >> 6, xx = i & 63;
            float v = x[(((size_t)b * CIN + c0 + cc) * HW + y) * HW + xx];
            shi[xx][cc] = __float2half_rn(v);
        }
        __syncthreads();
        for (int i = tid; i < 64 * 64; i += 512) {
            int xx = i >> 6;
            int wi = i & 63;
            int cc = wi << 1;
            int w  = wi & 7;
            int sp = ((w & 3) << 1) | (w >> 2);
            int ccp = (cc & ~15) | (sp << 1);
            size_t o = (((size_t)b * HW + y) * HW + xx) * CIN + c0 + ccp;
            *(uint32_t*)&g_xh[o] = *(const uint32_t*)&shi[xx][cc];
        }
        __syncthreads();
    }
}

// ---------------------------------------------------------------------------
// Main HMMA conv kernel
//   grid = (32 rowpairs, 8 couttiles, 8 b) = 2048 CTAs
//   128 threads (4 warps), warp = 64 cout x 32 px, 4 CTAs/SM
//   K: 32 chunks x 16 cin, 9 taps inner. 2-stage cp.async.
// smem per stage (26880 B):
//   W: [tap9][co64][32B] (ldmatrix-swizzled)  18432 B
//   X: [pos 4x66][32B, word-permuted]          8448 B
// ---------------------------------------------------------------------------
#define ST_BYTES 26880
#define XS_OFF   18432
#define SMEM_TOTAL (2 * ST_BYTES)

__global__ __launch_bounds__(128, 4)
void conv_hmma(const float* __restrict__ noise,
               const float* __restrict__ bias,
               float* __restrict__ out) {
    extern __shared__ __align__(128) char sm[];
    const uint32_t smb = smem_u32(sm);
    const int tid = threadIdx.x, lane = tid & 31, wn = tid >> 5;
    const int y0 = blockIdx.x * 2, cob = blockIdx.y * 64, b = blockIdx.z;
    const int g = lane >> 2, t = lane & 3;

    float acc[4][4][4];
    #pragma unroll
    for (int mf = 0; mf < 4; mf++)
        #pragma unroll
        for (int nf = 0; nf < 4; nf++)
            #pragma unroll
            for (int k = 0; k < 4; k++) acc[mf][nf][k] = 0.f;

    // ldmatrix lane offset; 16B-half h stored at (h ^ ((row>>2)&1))
    const uint32_t lmoff = (uint32_t)((lane & 15) * 32 +
                           ((((lane >> 4) ^ (lane >> 2)) & 1) * 16));

    const __half* wgbase = g_wh + ((size_t)(b * 9) * COUT + cob) * CIN;
    const __half* xgh = g_xh + (size_t)b * (HW * HW * CIN);

    auto load_chunk = [&](int cin0, int s) {
        const uint32_t wb = smb + s * ST_BYTES;
        // W: 9 taps x 64 co x 2 halves = 1152 x 16B
        for (int i = tid; i < 1152; i += 128) {
            int tap = i >> 7;
            int j   = i & 127;
            int co  = j >> 1;
            int h   = j & 1;
            const __half* src = wgbase + (size_t)tap * (COUT * CIN) + co * CIN + cin0 + h * 8;
            cp16(wb + tap * 2048 + co * 32 + ((h ^ ((co >> 2) & 1)) * 16), src, 16);
        }
        // X: 264 pos x 2 x 16B, zero-fill OOB
        const uint32_t xb = wb + XS_OFF;
        for (int i = tid; i < 528; i += 128) {
            int pos = i >> 1;
            int h2  = i & 1;
            int hy  = pos / 66;
            int hx  = pos - hy * 66;
            int gy = y0 - 1 + hy;
            int gx = hx - 1;
            bool ok = ((unsigned)gy < 64u) && ((unsigned)gx < 64u);
            int gyc = ok ? gy : 0, gxc = ok ? gx : 0;
            const __half* src = xgh + ((size_t)(gyc * 64 + gxc)) * CIN + cin0 + h2 * 8;
            cp16(xb + pos * 32 + h2 * 16, src, ok ? 16u : 0u);
        }
    };

    load_chunk(0, 0);
    cp_commit();

    for (int c = 0; c < 32; c++) {
        const int s = c & 1;
        if (c < 31) { load_chunk((c + 1) << 4, s ^ 1); cp_commit(); cp_wait<1>(); }
        else        { cp_wait<0>(); }
        __syncthreads();

        const uint32_t wsm = smb + s * ST_BYTES;
        const char* xhp = sm + s * ST_BYTES + XS_OFF;

        #pragma unroll 3
        for (int tap = 0; tap < 9; tap++) {
            const int dy = tap / 3, dx = tap - dy * 3;
            uint32_t A[4][4];
            #pragma unroll
            for (int mf = 0; mf < 4; mf++)
                ldmx4(A[mf], wsm + tap * 2048 + (uint32_t)((mf * 16) * 32) + lmoff);
            #pragma unroll
            for (int nf = 0; nf < 4; nf++) {
                const int pxb = wn * 32 + nf * 8;
                const int ph = ((pxb >> 6) + dy) * 66 + (pxb & 63) + dx + g;
                const uint2 bb = *(const uint2*)(xhp + ph * 32 + t * 8);
                #pragma unroll
                for (int mf = 0; mf < 4; mf++)
                    mma16816(acc[mf][nf], A[mf], bb.x, bb.y);
            }
        }
        __syncthreads();
    }

    // ---- epilogue: + noise + bias, leaky 0.2 ----
    #pragma unroll
    for (int mf = 0; mf < 4; mf++) {
        const int co = cob + mf * 16 + g;
        const float bi0 = bias[co];
        const float bi8 = bias[co + 8];
        #pragma unroll
        for (int nf = 0; nf < 4; nf++) {
            const int px = wn * 32 + nf * 8 + 2 * t;
            const int y  = y0 + (px >> 6);
            const int xo = px & 63;
            const size_t o0 = (((size_t)(b * COUT + co)) * HW + y) * HW + xo;
            const size_t o1 = o0 + (size_t)8 * HW * HW;
            float2 n0 = *(const float2*)(noise + o0);
            float2 n1 = *(const float2*)(noise + o1);
            float v0 = acc[mf][nf][0] + n0.x + bi0;
            float v1 = acc[mf][nf][1] + n0.y + bi0;
            float v2 = acc[mf][nf][2] + n1.x + bi8;
            float v3 = acc[mf][nf][3] + n1.y + bi8;
            float2 r0, r1;
            r0.x = (v0 >= 0.f) ? v0 : 0.2f * v0;
            r0.y = (v1 >= 0.f) ? v1 : 0.2f * v1;
            r1.x = (v2 >= 0.f) ? v2 : 0.2f * v2;
            r1.y = (v3 >= 0.f) ? v3 : 0.2f * v3;
            *(float2*)(out + o0) = r0;
            *(float2*)(out + o1) = r1;
        }
    }
}

// ---------------------------------------------------------------------------
extern "C" void kernel_launch(void* const* d_in, const int* in_sizes, int n_in,
                              void* d_out, int out_size) {
    const float* x      = (const float*)d_in[0];
    const float* w      = (const float*)d_in[1];
    const float* noise  = (const float*)d_in[2];
    const float* weight = (const float*)d_in[3];
    const float* aw     = (const float*)d_in[4];
    const float* ab     = (const float*)d_in[5];
    const float* bias   = (const float*)d_in[6];
    float* out = (float*)d_out;

    cudaFuncSetAttribute(conv_hmma, cudaFuncAttributeMaxDynamicSharedMemorySize,
                         SMEM_TOTAL);

    style_kernel<<<(B_ * CIN * 32 + 255) / 256, 256>>>(w, aw, ab);
    wsplit_kernel<<<COUT, CIN>>>(weight);
    xsplitT_kernel<<<dim3(HW, B_), 512>>>(x);
    conv_hmma<<<dim3(32, 8, B_), 128, SMEM_TOTAL>>>(noise, bias, out);
}